// round 13
// baseline (speedup 1.0000x reference)
#include <cuda_runtime.h>
#include <cuda_fp16.h>
#include <cstdint>

// ---------------- problem constants ----------------
#define BATCH 32
#define CIN   512
#define COUT  512
#define QL    4096
#define LPAD  4098          // 1 zero row of padding at each end (conv pad=1)

// GEMM tiling: persistent, CTA tile 128(M) x 256(N), 8 warps of 64x64, 1 CTA/SM
#define TILE_M 128
#define TILE_N 256
#define TILE_K 64           // c per chunk (128B fp16 rows, swizzled)
#define CPT 8               // c-chunks per tile; each chunk covers ALL 3 taps
#define NSTAGE 2
// stage: A = 3 taps * 128 rows * 128B = 49152 ; B = 258 rows * 128B = 33024
#define A_TAP_BYTES 16384
#define B_OFF 49152
#define STAGE_BYTES 82176
#define SMEM_DYN (NSTAGE * STAGE_BYTES)   // 164352 B

#define GRID_P 148
#define NTILES ((QL / TILE_N) * (COUT / TILE_M) * BATCH)   // 16*4*32 = 2048

// ---------------- device scratch ----------------
__device__ __align__(16) __half g_qx[(size_t)BATCH * LPAD * CIN];   // [b][l+1][c] quantized x (exact ints)
__device__ __align__(16) __half g_w2[(size_t)3 * COUT * CIN];       // [k][o][c]  w'' = qw*sw*sa (fp16)

// ---------------- base-ISA helpers ----------------
__device__ __forceinline__ uint32_t smem_u32(const void* p) {
    uint32_t a;
    asm("{ .reg .u64 t; cvta.to.shared.u64 t, %1; cvt.u32.u64 %0, t; }" : "=r"(a) : "l"(p));
    return a;
}
#define SWU(u, r) (((u) ^ ((r) & 7)) << 4)   // 16B-unit swizzle within a 128B row

__device__ __forceinline__ void cp_async16(uint32_t saddr, const void* gptr) {
    asm volatile("cp.async.cg.shared.global [%0], [%1], 16;" :: "r"(saddr), "l"(gptr));
}
#define CP_COMMIT() asm volatile("cp.async.commit_group;" ::: "memory")
#define CP_WAIT(n)  asm volatile("cp.async.wait_group %0;" :: "n"(n) : "memory")

__device__ __forceinline__ void ldm_x4(uint32_t& r0, uint32_t& r1, uint32_t& r2, uint32_t& r3, uint32_t a) {
    asm volatile("ldmatrix.sync.aligned.m8n8.x4.shared.b16 {%0,%1,%2,%3}, [%4];"
                 : "=r"(r0), "=r"(r1), "=r"(r2), "=r"(r3) : "r"(a));
}
__device__ __forceinline__ void mma16816(float& c0, float& c1, float& c2, float& c3,
                                         uint32_t a0, uint32_t a1, uint32_t a2, uint32_t a3,
                                         uint32_t b0, uint32_t b1) {
    asm("mma.sync.aligned.m16n8k16.row.col.f32.f16.f16.f32 "
        "{%0,%1,%2,%3}, {%4,%5,%6,%7}, {%8,%9}, {%0,%1,%2,%3};"
        : "+f"(c0), "+f"(c1), "+f"(c2), "+f"(c3)
        : "r"(a0), "r"(a1), "r"(a2), "r"(a3), "r"(b0), "r"(b1));
}

// ---------------- kernel 1: weight prep ----------------
// w'' = clip(rint(w/sw))*sw*sa, fp16; layout [k][o][c]
__global__ void prep_w_kernel(const float* __restrict__ w,
                              const float* __restrict__ a_scale,
                              const float* __restrict__ w_scale) {
    int o = blockIdx.x, c = threadIdx.x;
    float sw = fabsf(w_scale[o]) + 1e-8f;
    float sa = fabsf(a_scale[c]) + 1e-8f;
#pragma unroll
    for (int k = 0; k < 3; k++) {
        float v = w[((size_t)o * CIN + c) * 3 + k];
        float q = fminf(fmaxf(rintf(v / sw), -128.f), 127.f);
        float wpp = (q * sw) * sa;
        g_w2[((size_t)k * COUT + o) * CIN + c] = __float2half_rn(wpp);
    }
}

// ---------------- kernel 2: quantize + transpose x (conflict-free, pad fused) ----------------
__global__ void __launch_bounds__(256)
quant_kernel(const float* __restrict__ x, const float* __restrict__ a_scale) {
    __shared__ __half tile[128][66];
    const int tid  = threadIdx.x;
    const int warp = tid >> 5;
    const int lane = tid & 31;
    const int l0 = blockIdx.x * 64;
    const int c0 = blockIdx.y * 128;
    const int b  = blockIdx.z;

    if (blockIdx.x == 0 && tid < 32) {
        *reinterpret_cast<uint2*>(&g_qx[((size_t)b * LPAD + 0) * CIN + c0 + tid * 4]) =
            make_uint2(0u, 0u);
    }
    if (blockIdx.x == gridDim.x - 1 && tid < 32) {
        *reinterpret_cast<uint2*>(&g_qx[((size_t)b * LPAD + (LPAD - 1)) * CIN + c0 + tid * 4]) =
            make_uint2(0u, 0u);
    }

#pragma unroll
    for (int j = 0; j < 16; j++) {
        int ci = j * 8 + warp;
        int row = (ci & 3) * 32 + (ci >> 2);
        float s = fabsf(a_scale[c0 + ci]) + 1e-8f;
        float2 v = *reinterpret_cast<const float2*>(
            &x[((size_t)b * CIN + c0 + ci) * QL + l0 + lane * 2]);
        float q0 = fminf(fmaxf(rintf(v.x / s), -128.f), 127.f);
        float q1 = fminf(fmaxf(rintf(v.y / s), -128.f), 127.f);
        *reinterpret_cast<half2*>(&tile[row][lane * 2]) = __floats2half2_rn(q0, q1);
    }
    __syncthreads();

#pragma unroll
    for (int it = 0; it < 8; it++) {
        int l = it * 8 + warp;
        half2 p0 = __halves2half2(tile[lane +  0][l], tile[lane + 32][l]);
        half2 p1 = __halves2half2(tile[lane + 64][l], tile[lane + 96][l]);
        uint2 w;
        w.x = *reinterpret_cast<uint32_t*>(&p0);
        w.y = *reinterpret_cast<uint32_t*>(&p1);
        *reinterpret_cast<uint2*>(
            &g_qx[((size_t)b * LPAD + l0 + l + 1) * CIN + c0 + lane * 4]) = w;
    }
}

// ---------------- kernel 3: persistent GEMM-conv, fragment-pipelined ----------------
// 8 warps of 64x64; (tap,ks) flattened to 12 steps; af/bf double-buffered so
// step s+1's ldmatrix runs under step s's HMMA shadow.
__global__ void __launch_bounds__(256, 1)
qconv_gemm(const float* __restrict__ bias, float* __restrict__ out) {
    extern __shared__ __align__(16) char smem[];
    const uint32_t sbase = smem_u32(smem);
    const int tid  = threadIdx.x;
    const int wid  = tid >> 5;
    const int lane = tid & 31;
    const int bid  = blockIdx.x;

    // warp tile: 64(m) x 64(n); warp grid 2(m) x 4(n)
    const int wm = (wid & 1) * 64;
    const int wn = (wid >> 1) * 64;

    const uint4* gw = reinterpret_cast<const uint4*>(g_w2);
    const uint4* gx = reinterpret_cast<const uint4*>(g_qx);

    const int ntiles = (NTILES - 1 - bid) / GRID_P + 1;
    const int total  = ntiles * CPT;

    // flat-chunk loader (256 threads): 3 A tiles (12/thr) + 258-row B tile (<=9/thr)
    auto load_chunk = [&](int j) {
        const int t  = bid + (j >> 3) * GRID_P;
        const int cc = j & 7;
        const int b  = t >> 6;
        const int o0 = ((t >> 4) & 3) * TILE_M;
        const int L0 = (t & 15) * TILE_N;
        const uint32_t sb = sbase + (uint32_t)(j & 1) * STAGE_BYTES;
#pragma unroll
        for (int k = 0; k < 3; k++)
#pragma unroll
            for (int j2 = 0; j2 < 4; j2++) {
                int e = tid + j2 * 256;
                int r = e >> 3, u = e & 7;
                cp_async16(sb + k * A_TAP_BYTES + (uint32_t)(r * 128) + SWU(u, r),
                           &gw[(size_t)(k * COUT + o0 + r) * 64 + cc * 8 + u]);
            }
#pragma unroll
        for (int j2 = 0; j2 < 9; j2++) {
            int e = tid + j2 * 256;
            if (e < 2064) {
                int r = e >> 3, u = e & 7;
                cp_async16(sb + B_OFF + (uint32_t)(r * 128) + SWU(u, r),
                           &gx[((size_t)b * LPAD + L0 + r) * 64 + cc * 8 + u]);
            }
        }
    };

    float acc[4][8][4];
#pragma unroll
    for (int mi = 0; mi < 4; mi++)
#pragma unroll
        for (int nj = 0; nj < 8; nj++)
#pragma unroll
            for (int q = 0; q < 4; q++) acc[mi][nj][q] = 0.f;

    const int lrow = (lane & 7) + ((lane >> 3) & 1) * 8;
    const int lcol = (lane >> 4);

    uint32_t af[2][4][4], bf[2][4][4];

    // load fragments for step s = tap*4 + ks into buffer bufi
    auto load_frags = [&](uint32_t sb, int s, int bufi) {
        const int tap = s >> 2;
        const int u = (s & 3) * 2 + lcol;
#pragma unroll
        for (int t = 0; t < 4; t++) {
            int r = wn + t * 16 + lrow + tap;
            ldm_x4(bf[bufi][t][0], bf[bufi][t][1], bf[bufi][t][2], bf[bufi][t][3],
                   sb + B_OFF + r * 128 + SWU(u, r));
        }
#pragma unroll
        for (int t = 0; t < 4; t++) {
            int r = wm + t * 16 + lrow;
            ldm_x4(af[bufi][t][0], af[bufi][t][1], af[bufi][t][2], af[bufi][t][3],
                   sb + tap * A_TAP_BYTES + r * 128 + SWU(u, r));
        }
    };

    auto mma_step = [&](int bufi) {
#pragma unroll
        for (int mi = 0; mi < 4; mi++)
#pragma unroll
            for (int t = 0; t < 4; t++) {
                mma16816(acc[mi][t*2  ][0], acc[mi][t*2  ][1], acc[mi][t*2  ][2], acc[mi][t*2  ][3],
                         af[bufi][mi][0], af[bufi][mi][1], af[bufi][mi][2], af[bufi][mi][3],
                         bf[bufi][t][0], bf[bufi][t][2]);
                mma16816(acc[mi][t*2+1][0], acc[mi][t*2+1][1], acc[mi][t*2+1][2], acc[mi][t*2+1][3],
                         af[bufi][mi][0], af[bufi][mi][1], af[bufi][mi][2], af[bufi][mi][3],
                         bf[bufi][t][1], bf[bufi][t][3]);
            }
    };

    // prologue
    load_chunk(0); CP_COMMIT();

    for (int j = 0; j < total; j++) {
        CP_WAIT(0);                // this thread's group-j copies complete
        __syncthreads();           // stage j&1 visible CTA-wide; compute(j-1) done

        const uint32_t sb = sbase + (uint32_t)(j & 1) * STAGE_BYTES;
        load_frags(sb, 0, 0);
#pragma unroll
        for (int s = 0; s < 12; s++) {
            if (s + 1 < 12) load_frags(sb, s + 1, (s + 1) & 1);   // prefetch under HMMA shadow
            mma_step(s & 1);
            if (s == 0 && j + 1 < total) { load_chunk(j + 1); CP_COMMIT(); }
        }

        // ---- tile finished? register-only epilogue ----
        if ((j & 7) == 7) {
            const int t  = bid + (j >> 3) * GRID_P;
            const int b  = t >> 6;
            const int o0 = ((t >> 4) & 3) * TILE_M;
            const int L0 = (t & 15) * TILE_N;
#pragma unroll
            for (int mi = 0; mi < 4; mi++) {
                int r0 = wm + mi * 16 + (lane >> 2);
                int o_a = o0 + r0, o_b = o0 + r0 + 8;
                float bv0 = bias[o_a], bv1 = bias[o_b];
                float* pa = out + ((size_t)b * COUT + o_a) * QL + L0;
                float* pb = out + ((size_t)b * COUT + o_b) * QL + L0;
#pragma unroll
                for (int nj = 0; nj < 8; nj++) {
                    int col = wn + nj * 8 + (lane & 3) * 2;
                    float2 v0 = make_float2(acc[mi][nj][0] + bv0, acc[mi][nj][1] + bv0);
                    float2 v1 = make_float2(acc[mi][nj][2] + bv1, acc[mi][nj][3] + bv1);
                    *reinterpret_cast<float2*>(pa + col) = v0;
                    *reinterpret_cast<float2*>(pb + col) = v1;
                }
            }
#pragma unroll
            for (int mi = 0; mi < 4; mi++)
#pragma unroll
                for (int nj = 0; nj < 8; nj++)
#pragma unroll
                    for (int q = 0; q < 4; q++) acc[mi][nj][q] = 0.f;
        }
    }
}

// ---------------- launch ----------------
extern "C" void kernel_launch(void* const* d_in, const int* in_sizes, int n_in,
                              void* d_out, int out_size) {
    (void)in_sizes; (void)n_in; (void)out_size;
    const float* x       = (const float*)d_in[0];
    const float* weight  = (const float*)d_in[1];
    const float* bias    = (const float*)d_in[2];
    const float* a_scale = (const float*)d_in[3];
    const float* w_scale = (const float*)d_in[4];
    float* out = (float*)d_out;

    prep_w_kernel<<<COUT, CIN>>>(weight, a_scale, w_scale);
    quant_kernel<<<dim3(QL / 64, CIN / 128, BATCH), 256>>>(x, a_scale);

    cudaFuncSetAttribute(qconv_gemm, cudaFuncAttributeMaxDynamicSharedMemorySize, SMEM_DYN);
    qconv_gemm<<<GRID_P, 256, SMEM_DYN>>>(bias, out);
}